// round 13
// baseline (speedup 1.0000x reference)
#include <cuda_runtime.h>
#include <cuda_fp16.h>
#include <math.h>

#define B 4
#define S 256
#define E 256
#define H 8
#define DH 32
#define LD 128
#define NN 65536
#define NC 2
#define EPS 1e-5f

// ---------------- scratch ----------------
__device__ __align__(16) float g_q[B*H*S*DH];
__device__ __align__(16) float g_k[B*H*S*DH];
__device__ __align__(16) float g_v[B*H*S*DH];
__device__ __align__(16) float g_ctx[B*S*E];
__device__ __align__(16) float g_gpb[B*S*128];     // per-cluster global-half of h2 pre-activation
__device__ __align__(16) float g_wpart[4*128*256]; // wcomb K-split partials
__device__ __align__(16) float g_h16[B*S*16];      // leaky(fc1) hidden
__device__ __align__(16) float g_fc2inw[768*16];   // inw @ fc2
__device__ float g_posb[768];                      // inw @ fc2b
__device__ float g_bcomb[128];
__device__ int g_pref[S + 1];
// W2 local half folded fp16 (hi only), fragment-major: [chunk2][kstep4][ntile16][lane32] uint2
__device__ __align__(16) uint2 g_w2fh[2*4*16*32];
// W3 folded fp16 (hi only), fragment-major: [kstep8][ntile8][lane32]
__device__ __align__(16) uint2 g_w3fh[8*8*32];
__device__ float g_bi3[64];

// ---------------- helpers ----------------
__device__ __forceinline__ unsigned pack2h(float a0, float a1) {
    __half2 h = __floats2half2_rn(a0, a1);
    return *reinterpret_cast<unsigned*>(&h);
}
__device__ __forceinline__ void sts64(unsigned a, unsigned x, unsigned y) {
    asm volatile("st.shared.v2.b32 [%0],{%1,%2};" :: "r"(a), "r"(x), "r"(y) : "memory");
}
__device__ __forceinline__ void ldmx4(unsigned* r, unsigned addr) {
    asm volatile("ldmatrix.sync.aligned.m8n8.x4.shared.b16 {%0,%1,%2,%3},[%4];"
                 : "=r"(r[0]), "=r"(r[1]), "=r"(r[2]), "=r"(r[3]) : "r"(addr));
}
__device__ __forceinline__ void mma_f16(float &d0, float &d1, float &d2, float &d3,
                                        const unsigned* a, unsigned b0, unsigned b1) {
    asm volatile("mma.sync.aligned.m16n8k16.row.col.f32.f16.f16.f32 "
                 "{%0,%1,%2,%3},{%4,%5,%6,%7},{%8,%9},{%0,%1,%2,%3};"
                 : "+f"(d0), "+f"(d1), "+f"(d2), "+f"(d3)
                 : "r"(a[0]), "r"(a[1]), "r"(a[2]), "r"(a[3]), "r"(b0), "r"(b1));
}

// ---------------- kernel 1: fused setup (roles by blockIdx.x), 657 blocks x 256 ----------------
__global__ void setup1_kernel(const int* __restrict__ npc, const float* __restrict__ cent,
                              const float* __restrict__ fc1w, const float* __restrict__ fc1b,
                              const float* __restrict__ fc2w, const float* __restrict__ fc2b,
                              const float* __restrict__ inw, const float* __restrict__ ow,
                              const float* __restrict__ ob,
                              const float* __restrict__ w2, const float* __restrict__ cb2,
                              const float* __restrict__ gm2, const float* __restrict__ bt2,
                              const float* __restrict__ mu2, const float* __restrict__ va2,
                              const float* __restrict__ w3, const float* __restrict__ cb3,
                              const float* __restrict__ gm3, const float* __restrict__ bt3,
                              const float* __restrict__ mu3, const float* __restrict__ va3) {
    __shared__ float sbuf[8448];
    const int blk = blockIdx.x, t = threadIdx.x;

    if (blk < 512) {
        // ---- wcomb partials: c = blk>>2, ks = blk&3 ----
        float* wrow = sbuf;
        const int c = blk >> 2, ks = blk & 3;
        if (t < 64) {
            float s = gm2[c] * rsqrtf(va2[c] + EPS);
            wrow[t] = w2[c * 384 + 128 + ks * 64 + t] * s;
        }
        __syncthreads();
        float acc = 0.f;
#pragma unroll 8
        for (int ep = 0; ep < 64; ep++)
            acc += wrow[ep] * __ldg(&ow[(ks * 64 + ep) * 256 + t]);
        g_wpart[(ks * 128 + c) * 256 + t] = acc;
    } else if (blk == 512) {
        // ---- prefix sums ----
        int* vals = (int*)sbuf;
        vals[t] = npc[t];
        __syncthreads();
        if (t == 0) {
            int a = 0;
            for (int s = 0; s < S; s++) { g_pref[s] = a; a += vals[s]; }
            g_pref[S] = a;
        }
    } else if (blk < 577) {
        // ---- h16 = leaky(cent @ fc1^T + fc1b): 64 blocks, id = b*4096 + s*16 + j ----
        int id = (blk - 513) * 256 + t;
        int b = id >> 12, s = (id >> 4) & 255, j = id & 15;
        float c0 = cent[(b * S + s) * 2], c1 = cent[(b * S + s) * 2 + 1];
        float hh = fc1b[j] + c0 * fc1w[2 * j] + c1 * fc1w[2 * j + 1];
        g_h16[id] = (hh >= 0.f) ? hh : 0.01f * hh;
    } else if (blk < 625) {
        // ---- fc2inw[o][j] = sum_e inw[o][e]*fc2w[e][j]; posb[o] = sum_e inw[o][e]*fc2b[e] ----
        float* inwS = sbuf;          // 4096
        float* fcS  = sbuf + 4096;   // 4096
        float* fbS  = sbuf + 8192;   // 256
        const int o0 = (blk - 577) * 16;
        for (int p = 0; p < 4; p++) {
            int i4 = t + p * 256;
            int o = i4 >> 6, e4 = i4 & 63;
            *(float4*)&inwS[o * 256 + 4 * e4] = *(const float4*)&inw[(o0 + o) * 256 + 4 * e4];
            *(float4*)&fcS[i4 * 4] = *(const float4*)&fc2w[i4 * 4];
        }
        if (t < 64) *(float4*)&fbS[t * 4] = *(const float4*)&fc2b[t * 4];
        __syncthreads();
        const int ol = t >> 4, j = t & 15;
        float acc = 0.f, pb = 0.f;
#pragma unroll 8
        for (int e = 0; e < 256; e++) {
            float iv = inwS[ol * 256 + e];
            acc += iv * fcS[e * 16 + j];
            pb  += iv * fbS[e];
        }
        g_fc2inw[(o0 + ol) * 16 + j] = acc;
        if (j == 0) g_posb[o0 + ol] = pb;
    } else if (blk < 641) {
        // ---- wfrag2: 16 blocks ----
        int id = (blk - 625) * 256 + t;
        int lane = id & 31;
        int nt = (id >> 5) & 15;
        int ks = (id >> 9) & 3;
        int ch = id >> 11;
        int n = nt * 8 + (lane >> 2);
        int k0 = ch * 64 + ks * 16 + 2 * (lane & 3);
        float s = gm2[n] * rsqrtf(va2[n] + EPS);
        g_w2fh[id] = make_uint2(pack2h(w2[n * 384 + k0] * s,     w2[n * 384 + k0 + 1] * s),
                                pack2h(w2[n * 384 + k0 + 8] * s, w2[n * 384 + k0 + 9] * s));
    } else if (blk < 649) {
        // ---- wfrag3: 8 blocks ----
        int id = (blk - 641) * 256 + t;
        int lane = id & 31;
        int nt = (id >> 5) & 7;
        int ks = id >> 8;
        int n = nt * 8 + (lane >> 2);
        int k0 = ks * 16 + 2 * (lane & 3);
        float s = gm3[n] * rsqrtf(va3[n] + EPS);
        if (ks == 0 && (lane & 3) == 0)
            g_bi3[n] = (cb3[n] - mu3[n]) * s + bt3[n];
        g_w3fh[id] = make_uint2(pack2h(w3[n * 128 + k0] * s,     w3[n * 128 + k0 + 1] * s),
                                pack2h(w3[n * 128 + k0 + 8] * s, w3[n * 128 + k0 + 9] * s));
    } else {
        // ---- bcomb: 8 blocks x 16 c ----
        float* red = sbuf;
        const int ci = t >> 4, ei = t & 15;
        const int c = (blk - 649) * 16 + ci;
        float p = 0.f;
#pragma unroll
        for (int e = ei * 16; e < ei * 16 + 16; e++)
            p += w2[c * 384 + 128 + e] * ob[e];
        red[t] = p;
        __syncthreads();
        if (ei < 8) red[t] += red[t + 8];
        __syncthreads();
        if (ei < 4) red[t] += red[t + 4];
        __syncthreads();
        if (ei < 2) red[t] += red[t + 2];
        __syncthreads();
        if (ei == 0) {
            float s = gm2[c] * rsqrtf(va2[c] + EPS);
            g_bcomb[c] = (red[t] + red[t + 1]) * s + (cb2[c] - mu2[c]) * s + bt2[c];
        }
    }
}

// ---------------- kernel 2: qkv = gl^T @ inw^T + h16 @ fc2inw^T + posb + inb ----------------
// grid (12 chunks, 4 stiles, B) x 256; tile 64o x 64s, 4o x 4s per thread.
#define XQ_XS 0
#define XQ_WS 16640
#define XQ_FI 33792
#define XQ_H16 34816
#define XQ_PB 35840
#define XQ_FLOATS 35904

__global__ void xqkv_kernel(const float* __restrict__ gl, const float* __restrict__ inw,
                            const float* __restrict__ inb) {
    extern __shared__ float sh[];
    float* xs   = sh + XQ_XS;
    float* ws   = sh + XQ_WS;
    float* fc2i = sh + XQ_FI;
    float* h16s = sh + XQ_H16;
    float* pbs  = sh + XQ_PB;
    const int t = threadIdx.x;
    const int chunk = blockIdx.x, stile = blockIdx.y, b = blockIdx.z;
    const int s0 = stile * 64;

    for (int p = 0; p < 16; p++) {
        int i4 = t + p * 256;
        int s = i4 >> 6, e4 = i4 & 63;
        *(float4*)&xs[s * 260 + 4 * e4] = *(const float4*)&gl[((size_t)(s0 + s) * B + b) * E + 4 * e4];
    }
    for (int p = 0; p < 16; p++) {
        int i4 = t + p * 256;
        int o = i4 >> 6, k4 = i4 & 63;
        *(float4*)&ws[o * 268 + 4 * k4] = *(const float4*)&inw[(chunk * 64 + o) * 256 + 4 * k4];
    }
    {
        int o = t >> 2, q = t & 3;
        *(float4*)&fc2i[o * 16 + 4 * q] = *(const float4*)&g_fc2inw[(chunk * 64 + o) * 16 + 4 * q];
        *(float4*)&h16s[o * 16 + 4 * q] = *(const float4*)&g_h16[((size_t)b * S + s0 + o) * 16 + 4 * q];
    }
    if (t < 64) pbs[t] = g_posb[chunk * 64 + t];
    __syncthreads();

    const int ol = t & 15, sg = t >> 4;
    float acc[4][4];
#pragma unroll
    for (int oi = 0; oi < 4; oi++)
#pragma unroll
        for (int si = 0; si < 4; si++) acc[oi][si] = 0.f;

#pragma unroll 4
    for (int k4 = 0; k4 < 64; k4++) {
        float4 wv[4], av[4];
#pragma unroll
        for (int oi = 0; oi < 4; oi++) wv[oi] = *(float4*)&ws[(ol * 4 + oi) * 268 + 4 * k4];
#pragma unroll
        for (int si = 0; si < 4; si++) av[si] = *(float4*)&xs[(sg * 4 + si) * 260 + 4 * k4];
#pragma unroll
        for (int oi = 0; oi < 4; oi++)
#pragma unroll
            for (int si = 0; si < 4; si++)
                acc[oi][si] += wv[oi].x * av[si].x + wv[oi].y * av[si].y +
                               wv[oi].z * av[si].z + wv[oi].w * av[si].w;
    }

#pragma unroll
    for (int oi = 0; oi < 4; oi++) {
        int og = chunk * 64 + ol * 4 + oi;
        float base = inb[og] + pbs[ol * 4 + oi];
        int part = og >> 8, e = og & 255, hh = e >> 5, d = e & 31;
        float* dst = (part == 0) ? g_q : ((part == 1) ? g_k : g_v);
#pragma unroll
        for (int si = 0; si < 4; si++) {
            int s = s0 + sg * 4 + si;
            float v = acc[oi][si] + base;
#pragma unroll
            for (int j = 0; j < 16; j++)
                v += h16s[(sg * 4 + si) * 16 + j] * fc2i[(ol * 4 + oi) * 16 + j];
            dst[((b * H + hh) * S + s) * DH + d] = v;
        }
    }
}

// ---------------- kernel 3: attention, 8-way j-split, grid (8,H,B) x 256 ----------------
__global__ void attn_kernel() {
    extern __shared__ float sh[];
    float* ks  = sh;
    float* vs  = sh + 8192;
    float* pm  = vs + 8192;
    float* pl  = pm + 256;
    float* pac = pl + 256;
    const int t = threadIdx.x;
    const int b = blockIdx.z, h = blockIdx.y;
    const int base = ((b * H + h) * S) * DH;
    for (int i = t; i < 2048; i += 256) {
        ((float4*)ks)[i] = ((const float4*)(g_k + base))[i];
        ((float4*)vs)[i] = ((const float4*)(g_v + base))[i];
    }
    __syncthreads();
    const int q = t & 31, jh = t >> 5;
    const int qg = blockIdx.x * 32 + q;
    float qr[DH];
#pragma unroll
    for (int i = 0; i < 8; i++) ((float4*)qr)[i] = ((const float4*)(g_q + base + qg * DH))[i];
    const float scale = 0.17677669529663687f;
    float m = -1e30f, l = 0.f, acc[DH];
#pragma unroll
    for (int d = 0; d < DH; d++) acc[d] = 0.f;
    for (int j = jh * 32; j < jh * 32 + 32; j++) {
        float sc = 0.f;
#pragma unroll
        for (int d = 0; d < DH; d++) sc += qr[d] * ks[j * DH + d];
        sc *= scale;
        float mn = fmaxf(m, sc);
        float corr = __expf(m - mn);
        float p = __expf(sc - mn);
        m = mn;
        l = l * corr + p;
#pragma unroll
        for (int d = 0; d < DH; d++) acc[d] = acc[d] * corr + p * vs[j * DH + d];
    }
    pm[t] = m;
    pl[t] = l;
#pragma unroll
    for (int d = 0; d < DH; d++) pac[t * 33 + d] = acc[d];
    __syncthreads();
    if (t < 32) {
        float M = pm[t];
#pragma unroll
        for (int i = 1; i < 8; i++) M = fmaxf(M, pm[i * 32 + t]);
        float L = 0.f, vacc[DH];
#pragma unroll
        for (int d = 0; d < DH; d++) vacc[d] = 0.f;
#pragma unroll
        for (int i = 0; i < 8; i++) {
            float e = __expf(pm[i * 32 + t] - M);
            L += pl[i * 32 + t] * e;
#pragma unroll
            for (int d = 0; d < DH; d++) vacc[d] += pac[(i * 32 + t) * 33 + d] * e;
        }
        float inv = 1.f / L;
        int qo = blockIdx.x * 32 + t;
#pragma unroll
        for (int d = 0; d < DH; d++)
            g_ctx[(b * S + qo) * E + h * DH + d] = vacc[d] * inv;
    }
}

// ---------------- kernel 4: gpb = ctx @ W_comb^T + b_comb (partials summed inline) ----------------
// grid (8 chunks of 16 cols, 8 stiles, B) x 256
__global__ void gproj_kernel() {
    extern __shared__ float sh[];
    float* cs = sh;          // 32*260
    float* ws = sh + 8320;   // 16*268
    const int t = threadIdx.x;
    const int chunk = blockIdx.x, stile = blockIdx.y, b = blockIdx.z;
    const int s0 = stile * 32;
    for (int p = 0; p < 8; p++) {
        int i4 = t + p * 256;
        int s = i4 >> 6, e4 = i4 & 63;
        *(float4*)&cs[s * 260 + 4 * e4] = *(const float4*)&g_ctx[(b * S + s0 + s) * E + 4 * e4];
    }
    for (int p = 0; p < 4; p++) {
        int i4 = t + p * 256;
        int o = i4 >> 6, k4 = i4 & 63;
        int c = chunk * 16 + o;
        float4 v0 = *(const float4*)&g_wpart[(c) * 256 + 4 * k4];
        float4 v1 = *(const float4*)&g_wpart[(128 + c) * 256 + 4 * k4];
        float4 v2 = *(const float4*)&g_wpart[(256 + c) * 256 + 4 * k4];
        float4 v3 = *(const float4*)&g_wpart[(384 + c) * 256 + 4 * k4];
        v0.x += v1.x + v2.x + v3.x;
        v0.y += v1.y + v2.y + v3.y;
        v0.z += v1.z + v2.z + v3.z;
        v0.w += v1.w + v2.w + v3.w;
        *(float4*)&ws[o * 268 + 4 * k4] = v0;
    }
    __syncthreads();
    const int ol = t & 15, sg = t >> 4;
    float acc[2] = {0.f, 0.f};
#pragma unroll 8
    for (int k4 = 0; k4 < 64; k4++) {
        float4 wv = *(float4*)&ws[ol * 268 + 4 * k4];
#pragma unroll
        for (int i = 0; i < 2; i++) {
            float4 av = *(float4*)&cs[(sg + 16 * i) * 260 + 4 * k4];
            acc[i] += wv.x * av.x + wv.y * av.y + wv.z * av.z + wv.w * av.w;
        }
    }
    const int og = chunk * 16 + ol;
    const float bb = g_bcomb[og];
#pragma unroll
    for (int i = 0; i < 2; i++)
        g_gpb[(b * S + s0 + sg + 16 * i) * 128 + og] = acc[i] + bb;
}

// ---------------- kernel 5: fp16 mma.sync point-MLP (hi-only W, gpb init) ----------------
#define AB(i)   ((i) ? 18432 : 0)
#define MT_H3   0                     // overlay: 128*67*4 = 34304 <= 36864
#define MT_BI3  36864                 // 256
#define MT_W4S  37120                 // 512
#define MT_PREF 37632                 // 1028
#define MT_CID  38660                 // 512
#define MT_SIZE 39424

__global__ __launch_bounds__(256)
void mlp_mma_kernel(const float* __restrict__ lo, const float* __restrict__ w4,
                    const float* __restrict__ b4, float* __restrict__ out) {
    extern __shared__ __align__(16) char smc[];
    float* h3f  = (float*)(smc + MT_H3);
    float* bi3s = (float*)(smc + MT_BI3);
    float* w4s  = (float*)(smc + MT_W4S);
    int*   pref = (int*)(smc + MT_PREF);
    int*   cid  = (int*)(smc + MT_CID);
    const unsigned smemB = (unsigned)__cvta_generic_to_shared(smc);

    const int t = threadIdx.x;
    const int w = t >> 5, lane = t & 31;
    const int b = blockIdx.y;
    const int n0 = blockIdx.x * 128;

    if (t < 128) w4s[t] = w4[t];
    if (t >= 128 && t < 192) bi3s[t - 128] = g_bi3[t - 128];
    if (t < 256) pref[t] = g_pref[t];
    __syncthreads();
    if (t < 128) {
        int i = n0 + t;
        int s = 0;
#pragma unroll
        for (int step = 128; step >= 1; step >>= 1)
            if (s + step <= 255 && pref[s + step] <= i) s += step;
        cid[t] = s;
    }
    __syncthreads();

    const int grow = t >> 1, gkh = (t & 1) * 32;
    const int arow = (lane & 7) + ((lane >> 3) & 1) * 8;
    const int akb  = (lane >> 4) * 16;
    const int wm = w >> 2, wn = w & 3;
    const int g = lane >> 2, tg = lane & 3;

    // ---- gather chunk 0 (lo k 0-63) ----
    {
        const float* src = lo + ((size_t)(b * NN + n0 + grow)) * LD + gkh;
        unsigned hb = smemB + AB(0) + grow * 144 + gkh * 2;
#pragma unroll
        for (int j = 0; j < 8; j++) {
            float4 v = *(const float4*)(src + 4 * j);
            sts64(hb + 8 * j, pack2h(v.x, v.y), pack2h(v.z, v.w));
        }
    }

    // ---- init accumulators from gpb[cid] (fp32-exact global half) ----
    float acc[4][4][4];
#pragma unroll
    for (int mt = 0; mt < 4; mt++) {
        int r0 = wm * 64 + mt * 16 + g;
        const float* g0 = g_gpb + ((size_t)(b * S + cid[r0])) * 128;
        const float* g1 = g_gpb + ((size_t)(b * S + cid[r0 + 8])) * 128;
#pragma unroll
        for (int nt = 0; nt < 4; nt++) {
            int col = wn * 32 + nt * 8 + 2 * tg;
            float2 v0 = *(const float2*)(g0 + col);
            float2 v1 = *(const float2*)(g1 + col);
            acc[mt][nt][0] = v0.x; acc[mt][nt][1] = v0.y;
            acc[mt][nt][2] = v1.x; acc[mt][nt][3] = v1.y;
        }
    }
    __syncthreads();

    // ---- stage 1: 2 chunks of K=64 (lo only), hi-only ----
    for (int c = 0; c < 2; c++) {
        float4 nxt[8];
        if (c == 0) {
            const float* src = lo + ((size_t)(b * NN + n0 + grow)) * LD + 64 + gkh;
#pragma unroll
            for (int j = 0; j < 8; j++) nxt[j] = *(const float4*)(src + 4 * j);
        }
        const unsigned ah = smemB + AB(c);
#pragma unroll
        for (int ks = 0; ks < 4; ks++) {
            uint2 bh[4];
#pragma unroll
            for (int nt = 0; nt < 4; nt++) {
                int idx = ((c * 4 + ks) * 16 + wn * 4 + nt) * 32 + lane;
                bh[nt] = __ldg(&g_w2fh[idx]);
            }
#pragma unroll
            for (int mt = 0; mt < 4; mt++) {
                unsigned base = (wm * 64 + mt * 16 + arow) * 144 + ks * 32 + akb;
                unsigned fah[4];
                ldmx4(fah, ah + base);
#pragma unroll
                for (int nt = 0; nt < 4; nt++)
                    mma_f16(acc[mt][nt][0], acc[mt][nt][1], acc[mt][nt][2], acc[mt][nt][3],
                            fah, bh[nt].x, bh[nt].y);
            }
        }
        if (c == 0) {
            unsigned hb = smemB + AB(1) + grow * 144 + gkh * 2;
#pragma unroll
            for (int j = 0; j < 8; j++)
                sts64(hb + 8 * j, pack2h(nxt[j].x, nxt[j].y), pack2h(nxt[j].z, nxt[j].w));
        }
        __syncthreads();
    }

    // ---- stage1 epilogue: relu -> fp16 h2 into A buffers ----
    {
#pragma unroll
        for (int mt = 0; mt < 4; mt++) {
#pragma unroll
            for (int nt = 0; nt < 4; nt++) {
                int col = wn * 32 + nt * 8 + 2 * tg;
                int bufi = col >> 6;
                unsigned off = (col & 63) * 2;
                int r0 = wm * 64 + mt * 16 + g;
                *(unsigned*)(smc + AB(bufi) + r0 * 144 + off) =
                    pack2h(fmaxf(acc[mt][nt][0], 0.f), fmaxf(acc[mt][nt][1], 0.f));
                int r1 = r0 + 8;
                *(unsigned*)(smc + AB(bufi) + r1 * 144 + off) =
                    pack2h(fmaxf(acc[mt][nt][2], 0.f), fmaxf(acc[mt][nt][3], 0.f));
            }
        }
    }
    __syncthreads();

    // ---- stage 2: K=128 (8 ksteps), warp tile 32 pts x 32 ch, hi-only ----
    const int wm2 = w >> 1, wn2 = w & 1;
    float ac2[2][4][4];
#pragma unroll
    for (int mt = 0; mt < 2; mt++)
#pragma unroll
        for (int nt = 0; nt < 4; nt++)
#pragma unroll
            for (int r = 0; r < 4; r++) ac2[mt][nt][r] = 0.f;

#pragma unroll
    for (int ks = 0; ks < 8; ks++) {
        const unsigned ah = smemB + AB(ks >> 2);
        const int ki = ks & 3;
        uint2 bh[4];
#pragma unroll
        for (int nt = 0; nt < 4; nt++) {
            int idx = (ks * 8 + wn2 * 4 + nt) * 32 + lane;
            bh[nt] = __ldg(&g_w3fh[idx]);
        }
#pragma unroll
        for (int mt = 0; mt < 2; mt++) {
            unsigned base = (wm2 * 32 + mt * 16 + arow) * 144 + ki * 32 + akb;
            unsigned fah[4];
            ldmx4(fah, ah + base);
#pragma unroll
            for (int nt = 0; nt < 4; nt++)
                mma_f16(ac2[mt][nt][0], ac2[mt][nt][1], ac2[mt][nt][2], ac2[mt][nt][3],
                        fah, bh[nt].x, bh[nt].y);
        }
    }
    __syncthreads();

    // ---- stage2 epilogue: h3 fp32 overlay ----
    {
#pragma unroll
        for (int mt = 0; mt < 2; mt++) {
#pragma unroll
            for (int nt = 0; nt < 4; nt++) {
                int col = wn2 * 32 + nt * 8 + 2 * tg;
                float bia = bi3s[col], bib = bi3s[col + 1];
                int r0 = wm2 * 32 + mt * 16 + g;
                h3f[r0 * 67 + col]     = fmaxf(ac2[mt][nt][0] + bia, 0.f);
                h3f[r0 * 67 + col + 1] = fmaxf(ac2[mt][nt][1] + bib, 0.f);
                int r1 = r0 + 8;
                h3f[r1 * 67 + col]     = fmaxf(ac2[mt][nt][2] + bia, 0.f);
                h3f[r1 * 67 + col + 1] = fmaxf(ac2[mt][nt][3] + bib, 0.f);
            }
        }
    }
    __syncthreads();

    // ---- conv4 + transposed write ----
    if (t < 128) {
        const int p = t;
        float a0 = b4[0], a1 = b4[1];
#pragma unroll
        for (int k = 0; k < 64; k++) {
            float v = h3f[p * 67 + k];
            a0 += v * w4s[k];
            a1 += v * w4s[64 + k];
        }
        out[(size_t)(b * NC + 0) * NN + n0 + p] = a0;
        out[(size_t)(b * NC + 1) * NN + n0 + p] = a1;
    }
}

// ---------------- launch ----------------
extern "C" void kernel_launch(void* const* d_in, const int* in_sizes, int n_in,
                              void* d_out, int out_size) {
    const float* gl   = (const float*)d_in[0];
    const float* lo   = (const float*)d_in[1];
    const float* cent = (const float*)d_in[2];
    const int*   npc  = (const int*)  d_in[3];
    const float* fc1w = (const float*)d_in[4];
    const float* fc1b = (const float*)d_in[5];
    const float* fc2w = (const float*)d_in[6];
    const float* fc2b = (const float*)d_in[7];
    const float* inw  = (const float*)d_in[8];
    const float* inb  = (const float*)d_in[9];
    const float* ow   = (const float*)d_in[10];
    const float* ob   = (const float*)d_in[11];
    const float* w2   = (const float*)d_in[12];
    const float* cb2  = (const float*)d_in[13];
    const float* gm2  = (const float*)d_in[14];
    const float* bt2  = (const float*)d_in[15];
    const float* mu2  = (const float*)d_in[16];
    const float* va2  = (const float*)d_in[17];
    const float* w3   = (const float*)d_in[18];
    const float* cb3  = (const float*)d_in[19];
    const float* gm3  = (const float*)d_in[20];
    const float* bt3  = (const float*)d_in[21];
    const float* mu3  = (const float*)d_in[22];
    const float* va3  = (const float*)d_in[23];
    const float* w4   = (const float*)d_in[24];
    const float* b4   = (const float*)d_in[25];
    float* out = (float*)d_out;

    const int xqkv_smem = XQ_FLOATS * 4;                   // 143,616
    const int attn_smem = (8192 * 2 + 256 * 2 + 8448) * 4; // 101,376
    const int gp_smem   = (8320 + 16 * 268) * 4;           // 50,432

    cudaFuncSetAttribute(xqkv_kernel,    cudaFuncAttributeMaxDynamicSharedMemorySize, xqkv_smem);
    cudaFuncSetAttribute(attn_kernel,    cudaFuncAttributeMaxDynamicSharedMemorySize, attn_smem);
    cudaFuncSetAttribute(gproj_kernel,   cudaFuncAttributeMaxDynamicSharedMemorySize, gp_smem);
    cudaFuncSetAttribute(mlp_mma_kernel, cudaFuncAttributeMaxDynamicSharedMemorySize, MT_SIZE);

    setup1_kernel<<<657, 256>>>(npc, cent, fc1w, fc1b, fc2w, fc2b, inw, ow, ob,
                                w2, cb2, gm2, bt2, mu2, va2,
                                w3, cb3, gm3, bt3, mu3, va3);
    xqkv_kernel<<<dim3(12, 4, B), 256, xqkv_smem>>>(gl, inw, inb);
    attn_kernel<<<dim3(8, H, B), 256, attn_smem>>>();
    gproj_kernel<<<dim3(8, 8, B), 256, gp_smem>>>();
    mlp_mma_kernel<<<dim3(NN / 128, B), 256, MT_SIZE>>>(lo, w4, b4, out);
}

// round 15
// speedup vs baseline: 1.1015x; 1.1015x over previous
#include <cuda_runtime.h>
#include <cuda_fp16.h>
#include <math.h>

#define B 4
#define S 256
#define E 256
#define H 8
#define DH 32
#define LD 128
#define NN 65536
#define NC 2
#define EPS 1e-5f

// ---------------- scratch ----------------
__device__ __align__(16) float g_q[B*H*S*DH];
__device__ __align__(16) float g_k[B*H*S*DH];
__device__ __align__(16) float g_v[B*H*S*DH];
__device__ __align__(16) float g_ctx[B*S*E];
__device__ __align__(16) float g_gpb[B*S*128];     // per-cluster global-half of h2 pre-activation
__device__ __align__(16) float g_wpart[4*128*256]; // wcomb K-split partials
__device__ __align__(16) float g_h16[B*S*16];      // leaky(fc1) hidden
__device__ __align__(16) float g_fc2inw[768*16];   // inw @ fc2
__device__ float g_posb[768];                      // inw @ fc2b
__device__ float g_bcomb[128];
__device__ int g_pref[S + 1];
// W2 local half folded fp16 (hi only), fragment-major: [chunk2][kstep4][ntile16][lane32] uint2
__device__ __align__(16) uint2 g_w2fh[2*4*16*32];
// W3 folded fp16 (hi only), fragment-major: [kstep8][ntile8][lane32]
__device__ __align__(16) uint2 g_w3fh[8*8*32];
__device__ float g_bi3[64];

// ---------------- helpers ----------------
__device__ __forceinline__ unsigned pack2h(float a0, float a1) {
    __half2 h = __floats2half2_rn(a0, a1);
    return *reinterpret_cast<unsigned*>(&h);
}
__device__ __forceinline__ void sts64(unsigned a, unsigned x, unsigned y) {
    asm volatile("st.shared.v2.b32 [%0],{%1,%2};" :: "r"(a), "r"(x), "r"(y) : "memory");
}
__device__ __forceinline__ void ldmx4(unsigned* r, unsigned addr) {
    asm volatile("ldmatrix.sync.aligned.m8n8.x4.shared.b16 {%0,%1,%2,%3},[%4];"
                 : "=r"(r[0]), "=r"(r[1]), "=r"(r[2]), "=r"(r[3]) : "r"(addr));
}
__device__ __forceinline__ void mma_f16(float &d0, float &d1, float &d2, float &d3,
                                        const unsigned* a, unsigned b0, unsigned b1) {
    asm volatile("mma.sync.aligned.m16n8k16.row.col.f32.f16.f16.f32 "
                 "{%0,%1,%2,%3},{%4,%5,%6,%7},{%8,%9},{%0,%1,%2,%3};"
                 : "+f"(d0), "+f"(d1), "+f"(d2), "+f"(d3)
                 : "r"(a[0]), "r"(a[1]), "r"(a[2]), "r"(a[3]), "r"(b0), "r"(b1));
}

// ---------------- kernel 1: fused setup (roles by blockIdx.x), 657 blocks x 256 ----------------
__global__ void setup1_kernel(const int* __restrict__ npc, const float* __restrict__ cent,
                              const float* __restrict__ fc1w, const float* __restrict__ fc1b,
                              const float* __restrict__ fc2w, const float* __restrict__ fc2b,
                              const float* __restrict__ inw, const float* __restrict__ ow,
                              const float* __restrict__ ob,
                              const float* __restrict__ w2, const float* __restrict__ cb2,
                              const float* __restrict__ gm2, const float* __restrict__ bt2,
                              const float* __restrict__ mu2, const float* __restrict__ va2,
                              const float* __restrict__ w3, const float* __restrict__ cb3,
                              const float* __restrict__ gm3, const float* __restrict__ bt3,
                              const float* __restrict__ mu3, const float* __restrict__ va3) {
    __shared__ float sbuf[8448];
    const int blk = blockIdx.x, t = threadIdx.x;

    if (blk < 512) {
        // ---- wcomb partials: c = blk>>2, ks = blk&3 ----
        float* wrow = sbuf;
        const int c = blk >> 2, ks = blk & 3;
        if (t < 64) {
            float s = gm2[c] * rsqrtf(va2[c] + EPS);
            wrow[t] = w2[c * 384 + 128 + ks * 64 + t] * s;
        }
        __syncthreads();
        float acc = 0.f;
#pragma unroll 8
        for (int ep = 0; ep < 64; ep++)
            acc += wrow[ep] * __ldg(&ow[(ks * 64 + ep) * 256 + t]);
        g_wpart[(ks * 128 + c) * 256 + t] = acc;
    } else if (blk == 512) {
        // ---- prefix sums ----
        int* vals = (int*)sbuf;
        vals[t] = npc[t];
        __syncthreads();
        if (t == 0) {
            int a = 0;
            for (int s = 0; s < S; s++) { g_pref[s] = a; a += vals[s]; }
            g_pref[S] = a;
        }
    } else if (blk < 577) {
        // ---- h16 = leaky(cent @ fc1^T + fc1b): 64 blocks ----
        int id = (blk - 513) * 256 + t;
        int b = id >> 12, s = (id >> 4) & 255, j = id & 15;
        float c0 = cent[(b * S + s) * 2], c1 = cent[(b * S + s) * 2 + 1];
        float hh = fc1b[j] + c0 * fc1w[2 * j] + c1 * fc1w[2 * j + 1];
        g_h16[id] = (hh >= 0.f) ? hh : 0.01f * hh;
    } else if (blk < 625) {
        // ---- fc2inw[o][j] = sum_e inw[o][e]*fc2w[e][j]; posb[o] = sum_e inw[o][e]*fc2b[e] ----
        float* inwS = sbuf;          // 4096
        float* fcS  = sbuf + 4096;   // 4096
        float* fbS  = sbuf + 8192;   // 256
        const int o0 = (blk - 577) * 16;
        for (int p = 0; p < 4; p++) {
            int i4 = t + p * 256;
            int o = i4 >> 6, e4 = i4 & 63;
            *(float4*)&inwS[o * 256 + 4 * e4] = *(const float4*)&inw[(o0 + o) * 256 + 4 * e4];
            *(float4*)&fcS[i4 * 4] = *(const float4*)&fc2w[i4 * 4];
        }
        if (t < 64) *(float4*)&fbS[t * 4] = *(const float4*)&fc2b[t * 4];
        __syncthreads();
        const int ol = t >> 4, j = t & 15;
        float acc = 0.f, pb = 0.f;
#pragma unroll 8
        for (int e = 0; e < 256; e++) {
            float iv = inwS[ol * 256 + e];
            acc += iv * fcS[e * 16 + j];
            pb  += iv * fbS[e];
        }
        g_fc2inw[(o0 + ol) * 16 + j] = acc;
        if (j == 0) g_posb[o0 + ol] = pb;
    } else if (blk < 641) {
        // ---- wfrag2: 16 blocks ----
        int id = (blk - 625) * 256 + t;
        int lane = id & 31;
        int nt = (id >> 5) & 15;
        int ks = (id >> 9) & 3;
        int ch = id >> 11;
        int n = nt * 8 + (lane >> 2);
        int k0 = ch * 64 + ks * 16 + 2 * (lane & 3);
        float s = gm2[n] * rsqrtf(va2[n] + EPS);
        g_w2fh[id] = make_uint2(pack2h(w2[n * 384 + k0] * s,     w2[n * 384 + k0 + 1] * s),
                                pack2h(w2[n * 384 + k0 + 8] * s, w2[n * 384 + k0 + 9] * s));
    } else if (blk < 649) {
        // ---- wfrag3: 8 blocks ----
        int id = (blk - 641) * 256 + t;
        int lane = id & 31;
        int nt = (id >> 5) & 7;
        int ks = id >> 8;
        int n = nt * 8 + (lane >> 2);
        int k0 = ks * 16 + 2 * (lane & 3);
        float s = gm3[n] * rsqrtf(va3[n] + EPS);
        if (ks == 0 && (lane & 3) == 0)
            g_bi3[n] = (cb3[n] - mu3[n]) * s + bt3[n];
        g_w3fh[id] = make_uint2(pack2h(w3[n * 128 + k0] * s,     w3[n * 128 + k0 + 1] * s),
                                pack2h(w3[n * 128 + k0 + 8] * s, w3[n * 128 + k0 + 9] * s));
    } else {
        // ---- bcomb: 8 blocks x 16 c ----
        float* red = sbuf;
        const int ci = t >> 4, ei = t & 15;
        const int c = (blk - 649) * 16 + ci;
        float p = 0.f;
#pragma unroll
        for (int e = ei * 16; e < ei * 16 + 16; e++)
            p += w2[c * 384 + 128 + e] * ob[e];
        red[t] = p;
        __syncthreads();
        if (ei < 8) red[t] += red[t + 8];
        __syncthreads();
        if (ei < 4) red[t] += red[t + 4];
        __syncthreads();
        if (ei < 2) red[t] += red[t + 2];
        __syncthreads();
        if (ei == 0) {
            float s = gm2[c] * rsqrtf(va2[c] + EPS);
            g_bcomb[c] = (red[t] + red[t + 1]) * s + (cb2[c] - mu2[c]) * s + bt2[c];
        }
    }
}

// ---------------- kernel 2: qkv = gl^T @ inw^T + h16 @ fc2inw^T + posb + inb ----------------
// R12-proven tiling: 64o x 32s, ol = t&63 (bank-permutation rows), 2 blocks/SM.
#define XQ_XS  0                     // 32*260 = 8320
#define XQ_WS  8320                  // 64*268 = 17152
#define XQ_FI  25472                 // 64*17  = 1088 (stride 17: conflict-free)
#define XQ_H16 26560                 // 32*17  = 544
#define XQ_PB  27104                 // 64
#define XQ_FLOATS 27168

__global__ void xqkv_kernel(const float* __restrict__ gl, const float* __restrict__ inw,
                            const float* __restrict__ inb) {
    extern __shared__ float sh[];
    float* xs   = sh + XQ_XS;
    float* ws   = sh + XQ_WS;
    float* fc2i = sh + XQ_FI;
    float* h16s = sh + XQ_H16;
    float* pbs  = sh + XQ_PB;
    const int t = threadIdx.x;
    const int chunk = blockIdx.x, stile = blockIdx.y, b = blockIdx.z;
    const int s0 = stile * 32;

    for (int p = 0; p < 8; p++) {
        int i4 = t + p * 256;
        int s = i4 >> 6, e4 = i4 & 63;
        *(float4*)&xs[s * 260 + 4 * e4] = *(const float4*)&gl[((size_t)(s0 + s) * B + b) * E + 4 * e4];
    }
    for (int p = 0; p < 16; p++) {
        int i4 = t + p * 256;
        int o = i4 >> 6, k4 = i4 & 63;
        *(float4*)&ws[o * 268 + 4 * k4] = *(const float4*)&inw[(chunk * 64 + o) * 256 + 4 * k4];
    }
    for (int i = t; i < 64 * 16; i += 256) {
        int o = i >> 4, j = i & 15;
        fc2i[o * 17 + j] = g_fc2inw[(chunk * 64 + o) * 16 + j];
    }
    for (int i = t; i < 32 * 16; i += 256) {
        int o = i >> 4, j = i & 15;
        h16s[o * 17 + j] = g_h16[((size_t)b * S + s0 + o) * 16 + j];
    }
    if (t < 64) pbs[t] = g_posb[chunk * 64 + t];
    __syncthreads();

    const int ol = t & 63, sb = (t >> 6) * 8;
    float acc[8];
#pragma unroll
    for (int i = 0; i < 8; i++) acc[i] = 0.f;
#pragma unroll 8
    for (int k4 = 0; k4 < 64; k4++) {
        float4 wv = *(float4*)&ws[ol * 268 + 4 * k4];
#pragma unroll
        for (int i = 0; i < 8; i++) {
            float4 av = *(float4*)&xs[(sb + i) * 260 + 4 * k4];
            acc[i] += wv.x * av.x + wv.y * av.y + wv.z * av.z + wv.w * av.w;
        }
    }
    // pos correction: load fc2i row into regs (conflict-free), broadcast h16 rows
    float fr[16];
#pragma unroll
    for (int j = 0; j < 16; j++) fr[j] = fc2i[ol * 17 + j];

    const int og = chunk * 64 + ol;
    const float base = inb[og] + pbs[ol];
    const int part = og >> 8, e = og & 255, hh = e >> 5, d = e & 31;
    float* dst = (part == 0) ? g_q : ((part == 1) ? g_k : g_v);
#pragma unroll
    for (int i = 0; i < 8; i++) {
        float v = acc[i] + base;
#pragma unroll
        for (int j = 0; j < 16; j++)
            v += h16s[(sb + i) * 17 + j] * fr[j];
        int s = s0 + sb + i;
        dst[((b * H + hh) * S + s) * DH + d] = v;
    }
}

// ---------------- kernel 3: attention, 8-way j-split, grid (8,H,B) x 256 ----------------
__global__ void attn_kernel() {
    extern __shared__ float sh[];
    float* ks  = sh;
    float* vs  = sh + 8192;
    float* pm  = vs + 8192;
    float* pl  = pm + 256;
    float* pac = pl + 256;
    const int t = threadIdx.x;
    const int b = blockIdx.z, h = blockIdx.y;
    const int base = ((b * H + h) * S) * DH;
    for (int i = t; i < 2048; i += 256) {
        ((float4*)ks)[i] = ((const float4*)(g_k + base))[i];
        ((float4*)vs)[i] = ((const float4*)(g_v + base))[i];
    }
    __syncthreads();
    const int q = t & 31, jh = t >> 5;
    const int qg = blockIdx.x * 32 + q;
    float qr[DH];
#pragma unroll
    for (int i = 0; i < 8; i++) ((float4*)qr)[i] = ((const float4*)(g_q + base + qg * DH))[i];
    const float scale = 0.17677669529663687f;
    float m = -1e30f, l = 0.f, acc[DH];
#pragma unroll
    for (int d = 0; d < DH; d++) acc[d] = 0.f;
    for (int j = jh * 32; j < jh * 32 + 32; j++) {
        float sc = 0.f;
#pragma unroll
        for (int d = 0; d < DH; d++) sc += qr[d] * ks[j * DH + d];
        sc *= scale;
        float mn = fmaxf(m, sc);
        float corr = __expf(m - mn);
        float p = __expf(sc - mn);
        m = mn;
        l = l * corr + p;
#pragma unroll
        for (int d = 0; d < DH; d++) acc[d] = acc[d] * corr + p * vs[j * DH + d];
    }
    pm[t] = m;
    pl[t] = l;
#pragma unroll
    for (int d = 0; d < DH; d++) pac[t * 33 + d] = acc[d];
    __syncthreads();
    if (t < 32) {
        float M = pm[t];
#pragma unroll
        for (int i = 1; i < 8; i++) M = fmaxf(M, pm[i * 32 + t]);
        float L = 0.f, vacc[DH];
#pragma unroll
        for (int d = 0; d < DH; d++) vacc[d] = 0.f;
#pragma unroll
        for (int i = 0; i < 8; i++) {
            float e = __expf(pm[i * 32 + t] - M);
            L += pl[i * 32 + t] * e;
#pragma unroll
            for (int d = 0; d < DH; d++) vacc[d] += pac[(i * 32 + t) * 33 + d] * e;
        }
        float inv = 1.f / L;
        int qo = blockIdx.x * 32 + t;
#pragma unroll
        for (int d = 0; d < DH; d++)
            g_ctx[(b * S + qo) * E + h * DH + d] = vacc[d] * inv;
    }
}

// ---------------- kernel 4: gpb = ctx @ W_comb^T + b_comb (partials summed inline) ----------------
// grid (8 chunks of 16 cols, 8 stiles, B) x 256
__global__ void gproj_kernel() {
    extern __shared__ float sh[];
    float* cs = sh;          // 32*260
    float* ws = sh + 8320;   // 16*268
    const int t = threadIdx.x;
    const int chunk = blockIdx.x, stile = blockIdx.y, b = blockIdx.z;
    const int s0 = stile * 32;
    for (int p = 0; p < 8; p++) {
        int i4 = t + p * 256;
        int s = i4 >> 6, e4 = i4 & 63;
        *(float4*)&cs[s * 260 + 4 * e4] = *(const float4*)&g_ctx[(b * S + s0 + s) * E + 4 * e4];
    }
    for (int p = 0; p < 4; p++) {
        int i4 = t + p * 256;
        int o = i4 >> 6, k4 = i4 & 63;
        int c = chunk * 16 + o;
        float4 v0 = *(const float4*)&g_wpart[(c) * 256 + 4 * k4];
        float4 v1 = *(const float4*)&g_wpart[(128 + c) * 256 + 4 * k4];
        float4 v2 = *(const float4*)&g_wpart[(256 + c) * 256 + 4 * k4];
        float4 v3 = *(const float4*)&g_wpart[(384 + c) * 256 + 4 * k4];
        v0.x += v1.x + v2.x + v3.x;
        v0.y += v1.y + v2.y + v3.y;
        v0.z += v1.z + v2.z + v3.z;
        v0.w += v1.w + v2.w + v3.w;
        *(float4*)&ws[o * 268 + 4 * k4] = v0;
    }
    __syncthreads();
    const int ol = t & 15, sg = t >> 4;
    float acc[2] = {0.f, 0.f};
#pragma unroll 8
    for (int k4 = 0; k4 < 64; k4++) {
        float4 wv = *(float4*)&ws[ol * 268 + 4 * k4];
#pragma unroll
        for (int i = 0; i < 2; i++) {
            float4 av = *(float4*)&cs[(sg + 16 * i) * 260 + 4 * k4];
            acc[i] += wv.x * av.x + wv.y * av.y + wv.z * av.z + wv.w * av.w;
        }
    }
    const int og = chunk * 16 + ol;
    const float bb = g_bcomb[og];
#pragma unroll
    for (int i = 0; i < 2; i++)
        g_gpb[(b * S + s0 + sg + 16 * i) * 128 + og] = acc[i] + bb;
}

// ---------------- kernel 5: fp16 mma.sync point-MLP (hi-only W, gpb init) ----------------
#define AB(i)   ((i) ? 18432 : 0)
#define MT_H3   0                     // overlay: 128*67*4 = 34304 <= 36864
#define MT_BI3  36864                 // 256
#define MT_W4S  37120                 // 512
#define MT_PREF 37632                 // 1028
#define MT_CID  38660                 // 512
#define MT_SIZE 39424

__global__ __launch_bounds__(256)
void mlp_mma_kernel(const float* __restrict__ lo, const float* __restrict__ w4,
                    const float* __restrict__ b4, float* __restrict__ out) {
    extern __shared__ __align__(16) char smc[];
    float* h3f  = (float*)(smc + MT_H3);
    float* bi3s = (float*)(smc + MT_BI3);
    float* w4s  = (float*)(smc + MT_W4S);
    int*   pref = (int*)(smc + MT_PREF);
    int*   cid  = (int*)(smc + MT_CID);
    const unsigned smemB = (unsigned)__cvta_generic_to_shared(smc);

    const int t = threadIdx.x;
    const int w = t >> 5, lane = t & 31;
    const int b = blockIdx.y;
    const int n0 = blockIdx.x * 128;

    if (t < 128) w4s[t] = w4[t];
    if (t >= 128 && t < 192) bi3s[t - 128] = g_bi3[t - 128];
    if (t < 256) pref[t] = g_pref[t];
    __syncthreads();
    if (t < 128) {
        int i = n0 + t;
        int s = 0;
#pragma unroll
        for (int step = 128; step >= 1; step >>= 1)
            if (s + step <= 255 && pref[s + step] <= i) s += step;
        cid[t] = s;
    }
    __syncthreads();

    const int grow = t >> 1, gkh = (t & 1) * 32;
    const int arow = (lane & 7) + ((lane >> 3) & 1) * 8;
    const int akb  = (lane >> 4) * 16;
    const int wm = w >> 2, wn = w & 3;
    const int g = lane >> 2, tg = lane & 3;

    // ---- gather chunk 0 (lo k 0-63) ----
    {
        const float* src = lo + ((size_t)(b * NN + n0 + grow)) * LD + gkh;
        unsigned hb = smemB + AB(0) + grow * 144 + gkh * 2;
#pragma unroll
        for (int j = 0; j < 8; j++) {
            float4 v = *(const float4*)(src + 4 * j);
            sts64(hb + 8 * j, pack2h(v.x, v.y), pack2h(v.z, v.w));
        }
    }

    // ---- init accumulators from gpb[cid] (fp32-exact global half) ----
    float acc[4][4][4];
#pragma unroll
    for (int mt = 0; mt < 4; mt++) {
        int r0 = wm * 64 + mt * 16 + g;
        const float* g0 = g_gpb + ((size_t)(b * S + cid[r0])) * 128;
        const float* g1 = g_gpb + ((size_t)(b * S + cid[r0 + 8])) * 128;
#pragma unroll
        for (int nt = 0; nt < 4; nt++) {
            int col = wn * 32 + nt * 8 + 2 * tg;
            float2 v0 = *(const float2*)(g0 + col);
            float2 v1 = *(const float2*)(g1 + col);
            acc[mt][nt][0] = v0.x; acc[mt][nt][1] = v0.y;
            acc[mt][nt][2] = v1.x; acc[mt][nt][3] = v1.y;
        }
    }
    __syncthreads();

    // ---- stage 1: 2 chunks of K=64 (lo only), hi-only ----
    for (int c = 0; c < 2; c++) {
        float4 nxt[8];
        if (c == 0) {
            const float* src = lo + ((size_t)(b * NN + n0 + grow)) * LD + 64 + gkh;
#pragma unroll
            for (int j = 0; j < 8; j++) nxt[j] = *(const float4*)(src + 4 * j);
        }
        const unsigned ah = smemB + AB(c);
#pragma unroll
        for (int ks = 0; ks < 4; ks++) {
            uint2 bh[4];
#pragma unroll
            for (int nt = 0; nt < 4; nt++) {
                int idx = ((c * 4 + ks) * 16 + wn * 4 + nt) * 32 + lane;
                bh[nt] = __ldg(&g_w2fh[idx]);
            }
#pragma unroll
            for (int mt = 0; mt < 4; mt++) {
                unsigned base = (wm * 64 + mt * 16 + arow) * 144 + ks * 32 + akb;
                unsigned fah[4];
                ldmx4(fah, ah + base);
#pragma unroll
                for (int nt = 0; nt < 4; nt++)
                    mma_f16(acc[mt][nt][0], acc[mt][nt][1], acc[mt][nt][2], acc[mt][nt][3],
                            fah, bh[nt].x, bh[nt].y);
            }
        }
        if (c == 0) {
            unsigned hb = smemB + AB(1) + grow * 144 + gkh * 2;
#pragma unroll
            for (int j = 0; j < 8; j++)
                sts64(hb + 8 * j, pack2h(nxt[j].x, nxt[j].y), pack2h(nxt[j].z, nxt[j].w));
        }
        __syncthreads();
    }

    // ---- stage1 epilogue: relu -> fp16 h2 into A buffers ----
    {
#pragma unroll
        for (int mt = 0; mt < 4; mt++) {
#pragma unroll
            for (int nt = 0; nt < 4; nt++) {
                int col = wn * 32 + nt * 8 + 2 * tg;
                int bufi = col >> 6;
                unsigned off = (col & 63) * 2;
                int r0 = wm * 64 + mt * 16 + g;
                *(unsigned*)(smc + AB(bufi) + r0 * 144 + off) =
                    pack2h(fmaxf(acc[mt][nt][0], 0.f), fmaxf(acc[mt][nt][1], 0.f));
                int r1 = r0 + 8;
                *(unsigned*)(smc + AB(bufi) + r1 * 144 + off) =
                    pack2h(fmaxf(acc[mt][nt][2], 0.f), fmaxf(acc[mt][nt][3], 0.f));
            }
        }
    }
    __syncthreads();

    // ---- stage 2: K=128 (8 ksteps), warp tile 32 pts x 32 ch, hi-only ----
    const int wm2 = w >> 1, wn2 = w & 1;
    float ac2[2][4][4];
#pragma unroll
    for (int mt = 0; mt < 2; mt++)
#pragma unroll
        for (int nt = 0; nt < 4; nt++)
#pragma unroll
            for (int r = 0; r < 4; r++) ac2[mt][nt][r] = 0.f;

#pragma unroll
    for (int ks = 0; ks < 8; ks++) {
        const unsigned ah = smemB + AB(ks >> 2);
        const int ki = ks & 3;
        uint2 bh[4];
#pragma unroll
        for (int nt = 0; nt < 4; nt++) {
            int idx = (ks * 8 + wn2 * 4 + nt) * 32 + lane;
            bh[nt] = __ldg(&g_w3fh[idx]);
        }
#pragma unroll
        for (int mt = 0; mt < 2; mt++) {
            unsigned base = (wm2 * 32 + mt * 16 + arow) * 144 + ki * 32 + akb;
            unsigned fah[4];
            ldmx4(fah, ah + base);
#pragma unroll
            for (int nt = 0; nt < 4; nt++)
                mma_f16(ac2[mt][nt][0], ac2[mt][nt][1], ac2[mt][nt][2], ac2[mt][nt][3],
                        fah, bh[nt].x, bh[nt].y);
        }
    }
    __syncthreads();

    // ---- stage2 epilogue: h3 fp32 overlay ----
    {
#pragma unroll
        for (int mt = 0; mt < 2; mt++) {
#pragma unroll
            for (int nt = 0; nt < 4; nt++) {
                int col = wn2 * 32 + nt * 8 + 2 * tg;
                float bia = bi3s[col], bib = bi3s[col + 1];
                int r0 = wm2 * 32 + mt * 16 + g;
                h3f[r0 * 67 + col]     = fmaxf(ac2[mt][nt][0] + bia, 0.f);
                h3f[r0 * 67 + col + 1] = fmaxf(ac2[mt][nt][1] + bib, 0.f);
                int r1 = r0 + 8;
                h3f[r1 * 67 + col]     = fmaxf(ac2[mt][nt][2] + bia, 0.f);
                h3f[r1 * 67 + col + 1] = fmaxf(ac2[mt][nt][3] + bib, 0.f);
            }
        }
    }
    __syncthreads();

    // ---- conv4 + transposed write ----
    if (t < 128) {
        const int p = t;
        float a0 = b4[0], a1 = b4[1];
#pragma unroll
        for (int k = 0; k < 64; k++) {
            float v = h3f[p * 67 + k];
            a0 += v * w4s[k];
            a1 += v * w4s[64 + k];
        }
        out[(size_t)(b * NC + 0) * NN + n0 + p] = a0;
        out[(size_t)(b * NC + 1) * NN + n0 + p] = a1;
    }
}

// ---------------- launch ----------------
extern "C" void kernel_launch(void* const* d_in, const int* in_sizes, int n_in,
                              void* d_out, int out_size) {
    const float* gl   = (const float*)d_in[0];
    const float* lo   = (const float*)d_in[1];
    const float* cent = (const float*)d_in[2];
    const int*   npc  = (const int*)  d_in[3];
    const float* fc1w = (const float*)d_in[4];
    const float* fc1b = (const float*)d_in[5];
    const float* fc2w = (const float*)d_in[6];
    const float* fc2b = (const float*)d_in[7];
    const float* inw  = (const float*)d_in[8];
    const float* inb  = (const float*)d_in[9];
    const float* ow   = (const float*)d_in[10];
    const float* ob   = (const float*)d_in[11];
    const float* w2   = (const float*)d_in[12];
    const float* cb2  = (const float*)d_in[13];
    const float* gm2  = (const float*)d_in[14];
    const float* bt2  = (const float*)d_in[15];
    const float* mu2  = (const float*)d_in[16];
    const float* va2  = (const float*)d_in[17];
    const float* w3   = (const float*)d_in[18];
    const float* cb3  = (const float*)d_in[19];
    const float* gm3  = (const float*)d_in[20];
    const float* bt3  = (const float*)d_in[21];
    const float* mu3  = (const float*)d_in[22];
    const float* va3  = (const float*)d_in[23];
    const float* w4   = (const float*)d_in[24];
    const float* b4   = (const float*)d_in[25];
    float* out = (float*)d_out;

    const int xqkv_smem = XQ_FLOATS * 4;                   // 108,672
    const int attn_smem = (8192 * 2 + 256 * 2 + 8448) * 4; // 101,376
    const int gp_smem   = (8320 + 16 * 268) * 4;           // 50,432

    cudaFuncSetAttribute(xqkv_kernel,    cudaFuncAttributeMaxDynamicSharedMemorySize, xqkv_smem);
    cudaFuncSetAttribute(attn_kernel,    cudaFuncAttributeMaxDynamicSharedMemorySize, attn_smem);
    cudaFuncSetAttribute(gproj_kernel,   cudaFuncAttributeMaxDynamicSharedMemorySize, gp_smem);
    cudaFuncSetAttribute(mlp_mma_kernel, cudaFuncAttributeMaxDynamicSharedMemorySize, MT_SIZE);

    setup1_kernel<<<657, 256>>>(npc, cent, fc1w, fc1b, fc2w, fc2b, inw, ow, ob,
                                w2, cb2, gm2, bt2, mu2, va2,
                                w3, cb3, gm3, bt3, mu3, va3);
    xqkv_kernel<<<dim3(12, 8, B), 256, xqkv_smem>>>(gl, inw, inb);
    attn_kernel<<<dim3(8, H, B), 256, attn_smem>>>();
    gproj_kernel<<<dim3(8, 8, B), 256, gp_smem>>>();
    mlp_mma_kernel<<<dim3(NN / 128, B), 256, MT_SIZE>>>(lo, w4, b4, out);
}

// round 16
// speedup vs baseline: 1.2439x; 1.1293x over previous
#include <cuda_runtime.h>
#include <cuda_fp16.h>
#include <math.h>

#define B 4
#define S 256
#define E 256
#define H 8
#define DH 32
#define LD 128
#define NN 65536
#define NC 2
#define EPS 1e-5f

// ---------------- scratch ----------------
__device__ __align__(16) float g_q[B*H*S*DH];
__device__ __align__(16) float g_k[B*H*S*DH];
__device__ __align__(16) float g_v[B*H*S*DH];
__device__ __align__(16) float g_ctx[B*S*E];
__device__ __align__(16) float g_gpb[B*S*128];
__device__ __align__(16) float g_wpart[4*128*256];
__device__ __align__(16) float g_h16[B*S*16];
__device__ float g_posb[768];
__device__ float g_bcomb[128];
__device__ int g_pref[S + 1];
// W2 local half folded fp16 (hi only), fragment-major
__device__ __align__(16) uint2 g_w2fh[2*4*16*32];
// W3 folded fp16 (hi only), fragment-major
__device__ __align__(16) uint2 g_w3fh[8*8*32];
// inw fp16 split, fragment-major: [kstep16][ntile96][lane32]
__device__ __align__(16) uint2 g_inwfh[16*96*32];
__device__ __align__(16) uint2 g_inwfl[16*96*32];
// fc2inw fp16 split, fragment-major: [ntile96][lane32]
__device__ __align__(16) uint2 g_fc2fh[96*32];
__device__ __align__(16) uint2 g_fc2fl[96*32];
__device__ float g_bi3[64];

// ---------------- helpers ----------------
__device__ __forceinline__ unsigned pack2h(float a0, float a1) {
    __half2 h = __floats2half2_rn(a0, a1);
    return *reinterpret_cast<unsigned*>(&h);
}
__device__ __forceinline__ unsigned pack_split2h(float a0, float a1, unsigned &lo2) {
    __half h0 = __float2half_rn(a0), h1 = __float2half_rn(a1);
    __half l0 = __float2half_rn(a0 - __half2float(h0));
    __half l1 = __float2half_rn(a1 - __half2float(h1));
    lo2 = ((unsigned)__half_as_ushort(l1) << 16) | (unsigned)__half_as_ushort(l0);
    return ((unsigned)__half_as_ushort(h1) << 16) | (unsigned)__half_as_ushort(h0);
}
__device__ __forceinline__ void sts64(unsigned a, unsigned x, unsigned y) {
    asm volatile("st.shared.v2.b32 [%0],{%1,%2};" :: "r"(a), "r"(x), "r"(y) : "memory");
}
__device__ __forceinline__ void ldmx4(unsigned* r, unsigned addr) {
    asm volatile("ldmatrix.sync.aligned.m8n8.x4.shared.b16 {%0,%1,%2,%3},[%4];"
                 : "=r"(r[0]), "=r"(r[1]), "=r"(r[2]), "=r"(r[3]) : "r"(addr));
}
__device__ __forceinline__ void mma_f16(float &d0, float &d1, float &d2, float &d3,
                                        const unsigned* a, unsigned b0, unsigned b1) {
    asm volatile("mma.sync.aligned.m16n8k16.row.col.f32.f16.f16.f32 "
                 "{%0,%1,%2,%3},{%4,%5,%6,%7},{%8,%9},{%0,%1,%2,%3};"
                 : "+f"(d0), "+f"(d1), "+f"(d2), "+f"(d3)
                 : "r"(a[0]), "r"(a[1]), "r"(a[2]), "r"(a[3]), "r"(b0), "r"(b1));
}

// ---------------- kernel 1: fused setup (roles by blockIdx.x), 849 blocks x 256 ----------------
__global__ void setup1_kernel(const int* __restrict__ npc, const float* __restrict__ cent,
                              const float* __restrict__ fc1w, const float* __restrict__ fc1b,
                              const float* __restrict__ fc2w, const float* __restrict__ fc2b,
                              const float* __restrict__ inw, const float* __restrict__ ow,
                              const float* __restrict__ ob,
                              const float* __restrict__ w2, const float* __restrict__ cb2,
                              const float* __restrict__ gm2, const float* __restrict__ bt2,
                              const float* __restrict__ mu2, const float* __restrict__ va2,
                              const float* __restrict__ w3, const float* __restrict__ cb3,
                              const float* __restrict__ gm3, const float* __restrict__ bt3,
                              const float* __restrict__ mu3, const float* __restrict__ va3) {
    __shared__ float sbuf[8448];
    const int blk = blockIdx.x, t = threadIdx.x;

    if (blk < 512) {
        // ---- wcomb partials ----
        float* wrow = sbuf;
        const int c = blk >> 2, ks = blk & 3;
        if (t < 64) {
            float s = gm2[c] * rsqrtf(va2[c] + EPS);
            wrow[t] = w2[c * 384 + 128 + ks * 64 + t] * s;
        }
        __syncthreads();
        float acc = 0.f;
#pragma unroll 8
        for (int ep = 0; ep < 64; ep++)
            acc += wrow[ep] * __ldg(&ow[(ks * 64 + ep) * 256 + t]);
        g_wpart[(ks * 128 + c) * 256 + t] = acc;
    } else if (blk == 512) {
        // ---- prefix sums ----
        int* vals = (int*)sbuf;
        vals[t] = npc[t];
        __syncthreads();
        if (t == 0) {
            int a = 0;
            for (int s = 0; s < S; s++) { g_pref[s] = a; a += vals[s]; }
            g_pref[S] = a;
        }
    } else if (blk < 577) {
        // ---- h16 = leaky(cent @ fc1^T + fc1b) ----
        int id = (blk - 513) * 256 + t;
        int b = id >> 12, s = (id >> 4) & 255, j = id & 15;
        float c0 = cent[(b * S + s) * 2], c1 = cent[(b * S + s) * 2 + 1];
        float hh = fc1b[j] + c0 * fc1w[2 * j] + c1 * fc1w[2 * j + 1];
        g_h16[id] = (hh >= 0.f) ? hh : 0.01f * hh;
    } else if (blk < 625) {
        // ---- fc2inw rows o0..o0+15 -> fragments + posb ----
        float* inwS = sbuf;          // 4096
        float* fcS  = sbuf + 4096;   // 4096 (later reused as acc table)
        float* fbS  = sbuf + 8192;   // 256
        const int o0 = (blk - 577) * 16;
        for (int p = 0; p < 4; p++) {
            int i4 = t + p * 256;
            int o = i4 >> 6, e4 = i4 & 63;
            *(float4*)&inwS[o * 256 + 4 * e4] = *(const float4*)&inw[(o0 + o) * 256 + 4 * e4];
            *(float4*)&fcS[i4 * 4] = *(const float4*)&fc2w[i4 * 4];
        }
        if (t < 64) *(float4*)&fbS[t * 4] = *(const float4*)&fc2b[t * 4];
        __syncthreads();
        const int ol = t >> 4, j = t & 15;
        float acc = 0.f, pb = 0.f;
#pragma unroll 8
        for (int e = 0; e < 256; e++) {
            float iv = inwS[ol * 256 + e];
            acc += iv * fcS[e * 16 + j];
            pb  += iv * fbS[e];
        }
        if (j == 0) g_posb[o0 + ol] = pb;
        __syncthreads();               // done reading fcS
        fcS[ol * 16 + j] = acc;        // acc table
        __syncthreads();
        if (t < 64) {
            int ntl = t >> 5, lane = t & 31;
            int rl = ntl * 8 + (lane >> 2);
            int k0 = 2 * (lane & 3);
            unsigned l0, l1;
            unsigned h0 = pack_split2h(fcS[rl * 16 + k0], fcS[rl * 16 + k0 + 1], l0);
            unsigned h1 = pack_split2h(fcS[rl * 16 + k0 + 8], fcS[rl * 16 + k0 + 9], l1);
            int gnt = (blk - 577) * 2 + ntl;
            g_fc2fh[gnt * 32 + lane] = make_uint2(h0, h1);
            g_fc2fl[gnt * 32 + lane] = make_uint2(l0, l1);
        }
    } else if (blk < 641) {
        // ---- wfrag2 ----
        int id = (blk - 625) * 256 + t;
        int lane = id & 31;
        int nt = (id >> 5) & 15;
        int ks = (id >> 9) & 3;
        int ch = id >> 11;
        int n = nt * 8 + (lane >> 2);
        int k0 = ch * 64 + ks * 16 + 2 * (lane & 3);
        float s = gm2[n] * rsqrtf(va2[n] + EPS);
        g_w2fh[id] = make_uint2(pack2h(w2[n * 384 + k0] * s,     w2[n * 384 + k0 + 1] * s),
                                pack2h(w2[n * 384 + k0 + 8] * s, w2[n * 384 + k0 + 9] * s));
    } else if (blk < 649) {
        // ---- wfrag3 ----
        int id = (blk - 641) * 256 + t;
        int lane = id & 31;
        int nt = (id >> 5) & 7;
        int ks = id >> 8;
        int n = nt * 8 + (lane >> 2);
        int k0 = ks * 16 + 2 * (lane & 3);
        float s = gm3[n] * rsqrtf(va3[n] + EPS);
        if (ks == 0 && (lane & 3) == 0)
            g_bi3[n] = (cb3[n] - mu3[n]) * s + bt3[n];
        g_w3fh[id] = make_uint2(pack2h(w3[n * 128 + k0] * s,     w3[n * 128 + k0 + 1] * s),
                                pack2h(w3[n * 128 + k0 + 8] * s, w3[n * 128 + k0 + 9] * s));
    } else if (blk < 657) {
        // ---- bcomb ----
        float* red = sbuf;
        const int ci = t >> 4, ei = t & 15;
        const int c = (blk - 649) * 16 + ci;
        float p = 0.f;
#pragma unroll
        for (int e = ei * 16; e < ei * 16 + 16; e++)
            p += w2[c * 384 + 128 + e] * ob[e];
        red[t] = p;
        __syncthreads();
        if (ei < 8) red[t] += red[t + 8];
        __syncthreads();
        if (ei < 4) red[t] += red[t + 4];
        __syncthreads();
        if (ei < 2) red[t] += red[t + 2];
        __syncthreads();
        if (ei == 0) {
            float s = gm2[c] * rsqrtf(va2[c] + EPS);
            g_bcomb[c] = (red[t] + red[t + 1]) * s + (cb2[c] - mu2[c]) * s + bt2[c];
        }
    } else {
        // ---- inw fragments (hi+lo): 192 blocks ----
        int id = (blk - 657) * 256 + t;    // 0..49151
        int lane = id & 31;
        int rest = id >> 5;
        int nt = rest % 96, ks = rest / 96;
        int n = nt * 8 + (lane >> 2);
        int k0 = ks * 16 + 2 * (lane & 3);
        unsigned l0, l1;
        unsigned h0 = pack_split2h(inw[n * 256 + k0],     inw[n * 256 + k0 + 1], l0);
        unsigned h1 = pack_split2h(inw[n * 256 + k0 + 8], inw[n * 256 + k0 + 9], l1);
        g_inwfh[id] = make_uint2(h0, h1);
        g_inwfl[id] = make_uint2(l0, l1);
    }
}

// ---------------- kernel 2: qkv via 3-term fp16-split mma ----------------
// A = [gl_slice(K=256) | h16(K=16)], B = [inw | fc2inw] fragments, M-tile 64, N-tile 64.
// grid (12 nchunks, 4 mtiles, B) x 256. A buffers: hi 64*144, lo 64*144.
#define XA_H 0
#define XA_L 9216
#define XQ_SMEM 18432

__global__ __launch_bounds__(256)
void xqkv_kernel(const float* __restrict__ gl, const float* __restrict__ inb) {
    extern __shared__ __align__(16) char smc[];
    const unsigned smemB = (unsigned)__cvta_generic_to_shared(smc);
    const int t = threadIdx.x;
    const int w = t >> 5, lane = t & 31;
    const int chunk = blockIdx.x, mtile = blockIdx.y, b = blockIdx.z;
    const int s0 = mtile * 64;

    const int arow = (lane & 7) + ((lane >> 3) & 1) * 8;
    const int akb  = (lane >> 4) * 16;
    const int wm = w >> 2, wn = w & 3;      // wm: 32-row halves, wn: 16-col tiles
    const int g = lane >> 2, tg = lane & 3;

    float acc[2][2][4];
#pragma unroll
    for (int mt = 0; mt < 2; mt++)
#pragma unroll
        for (int nt = 0; nt < 2; nt++)
#pragma unroll
            for (int r = 0; r < 4; r++) acc[mt][nt][r] = 0.f;

    // ---- 4 chunks of K=64 from gl ----
    const int grow = t >> 2, gq = t & 3;    // 64 rows, 4 threads/row (16 floats each)
    for (int c = 0; c < 4; c++) {
        {
            const float* src = gl + ((size_t)(s0 + grow) * B + b) * E + c * 64 + gq * 16;
            unsigned hb = smemB + XA_H + grow * 144 + gq * 32;
            unsigned lb = smemB + XA_L + grow * 144 + gq * 32;
#pragma unroll
            for (int j = 0; j < 4; j++) {
                float4 v = *(const float4*)(src + 4 * j);
                unsigned l0, l1;
                unsigned h0 = pack_split2h(v.x, v.y, l0);
                unsigned h1 = pack_split2h(v.z, v.w, l1);
                sts64(hb + 8 * j, h0, h1);
                sts64(lb + 8 * j, l0, l1);
            }
        }
        __syncthreads();
#pragma unroll
        for (int ks = 0; ks < 4; ks++) {
            uint2 bh[2], bl[2];
#pragma unroll
            for (int nt = 0; nt < 2; nt++) {
                int idx = ((c * 4 + ks) * 96 + chunk * 8 + wn * 2 + nt) * 32 + lane;
                bh[nt] = __ldg(&g_inwfh[idx]);
                bl[nt] = __ldg(&g_inwfl[idx]);
            }
#pragma unroll
            for (int mt = 0; mt < 2; mt++) {
                unsigned base = (wm * 32 + mt * 16 + arow) * 144 + ks * 32 + akb;
                unsigned fah[4], fal[4];
                ldmx4(fah, smemB + XA_H + base);
                ldmx4(fal, smemB + XA_L + base);
#pragma unroll
                for (int nt = 0; nt < 2; nt++) {
                    mma_f16(acc[mt][nt][0], acc[mt][nt][1], acc[mt][nt][2], acc[mt][nt][3],
                            fah, bh[nt].x, bh[nt].y);
                    mma_f16(acc[mt][nt][0], acc[mt][nt][1], acc[mt][nt][2], acc[mt][nt][3],
                            fah, bl[nt].x, bl[nt].y);
                    mma_f16(acc[mt][nt][0], acc[mt][nt][1], acc[mt][nt][2], acc[mt][nt][3],
                            fal, bh[nt].x, bh[nt].y);
                }
            }
        }
        __syncthreads();
    }

    // ---- h16 kstep (K=16) ----
    if (t < 128) {
        int row = t >> 1, half = t & 1;
        const float* src = g_h16 + ((size_t)b * S + s0 + row) * 16 + half * 8;
        unsigned hb = smemB + XA_H + row * 144 + half * 16;
        unsigned lb = smemB + XA_L + row * 144 + half * 16;
#pragma unroll
        for (int j = 0; j < 2; j++) {
            float4 v = *(const float4*)(src + 4 * j);
            unsigned l0, l1;
            unsigned h0 = pack_split2h(v.x, v.y, l0);
            unsigned h1 = pack_split2h(v.z, v.w, l1);
            sts64(hb + 8 * j, h0, h1);
            sts64(lb + 8 * j, l0, l1);
        }
    }
    __syncthreads();
    {
        uint2 bh[2], bl[2];
#pragma unroll
        for (int nt = 0; nt < 2; nt++) {
            int idx = (chunk * 8 + wn * 2 + nt) * 32 + lane;
            bh[nt] = __ldg(&g_fc2fh[idx]);
            bl[nt] = __ldg(&g_fc2fl[idx]);
        }
#pragma unroll
        for (int mt = 0; mt < 2; mt++) {
            unsigned base = (wm * 32 + mt * 16 + arow) * 144 + akb;
            unsigned fah[4], fal[4];
            ldmx4(fah, smemB + XA_H + base);
            ldmx4(fal, smemB + XA_L + base);
#pragma unroll
            for (int nt = 0; nt < 2; nt++) {
                mma_f16(acc[mt][nt][0], acc[mt][nt][1], acc[mt][nt][2], acc[mt][nt][3],
                        fah, bh[nt].x, bh[nt].y);
                mma_f16(acc[mt][nt][0], acc[mt][nt][1], acc[mt][nt][2], acc[mt][nt][3],
                        fah, bl[nt].x, bl[nt].y);
                mma_f16(acc[mt][nt][0], acc[mt][nt][1], acc[mt][nt][2], acc[mt][nt][3],
                        fal, bh[nt].x, bh[nt].y);
            }
        }
    }

    // ---- epilogue: bias + scatter to q/k/v ----
#pragma unroll
    for (int mt = 0; mt < 2; mt++) {
#pragma unroll
        for (int nt = 0; nt < 2; nt++) {
            int col = wn * 16 + nt * 8 + 2 * tg;
            int og = chunk * 64 + col;
            float b0 = __ldg(&inb[og]) + g_posb[og];
            float b1 = __ldg(&inb[og + 1]) + g_posb[og + 1];
            int part = og >> 8, e = og & 255, hh = e >> 5, d = e & 31;
            float* dst = (part == 0) ? g_q : ((part == 1) ? g_k : g_v);
            int r0 = wm * 32 + mt * 16 + g;
            int s = s0 + r0;
            dst[((b * H + hh) * S + s) * DH + d]     = acc[mt][nt][0] + b0;
            dst[((b * H + hh) * S + s) * DH + d + 1] = acc[mt][nt][1] + b1;
            int s2 = s + 8;
            dst[((b * H + hh) * S + s2) * DH + d]     = acc[mt][nt][2] + b0;
            dst[((b * H + hh) * S + s2) * DH + d + 1] = acc[mt][nt][3] + b1;
        }
    }
}

// ---------------- kernel 3: attention, 8-way j-split, grid (8,H,B) x 256 ----------------
__global__ void attn_kernel() {
    extern __shared__ float sh[];
    float* ks  = sh;
    float* vs  = sh + 8192;
    float* pm  = vs + 8192;
    float* pl  = pm + 256;
    float* pac = pl + 256;
    const int t = threadIdx.x;
    const int b = blockIdx.z, h = blockIdx.y;
    const int base = ((b * H + h) * S) * DH;
    for (int i = t; i < 2048; i += 256) {
        ((float4*)ks)[i] = ((const float4*)(g_k + base))[i];
        ((float4*)vs)[i] = ((const float4*)(g_v + base))[i];
    }
    __syncthreads();
    const int q = t & 31, jh = t >> 5;
    const int qg = blockIdx.x * 32 + q;
    float qr[DH];
#pragma unroll
    for (int i = 0; i < 8; i++) ((float4*)qr)[i] = ((const float4*)(g_q + base + qg * DH))[i];
    const float scale = 0.17677669529663687f;
    float m = -1e30f, l = 0.f, acc[DH];
#pragma unroll
    for (int d = 0; d < DH; d++) acc[d] = 0.f;
    for (int j = jh * 32; j < jh * 32 + 32; j++) {
        float sc = 0.f;
#pragma unroll
        for (int d = 0; d < DH; d++) sc += qr[d] * ks[j * DH + d];
        sc *= scale;
        float mn = fmaxf(m, sc);
        float corr = __expf(m - mn);
        float p = __expf(sc - mn);
        m = mn;
        l = l * corr + p;
#pragma unroll
        for (int d = 0; d < DH; d++) acc[d] = acc[d] * corr + p * vs[j * DH + d];
    }
    pm[t] = m;
    pl[t] = l;
#pragma unroll
    for (int d = 0; d < DH; d++) pac[t * 33 + d] = acc[d];
    __syncthreads();
    if (t < 32) {
        float M = pm[t];
#pragma unroll
        for (int i = 1; i < 8; i++) M = fmaxf(M, pm[i * 32 + t]);
        float L = 0.f, vacc[DH];
#pragma unroll
        for (int d = 0; d < DH; d++) vacc[d] = 0.f;
#pragma unroll
        for (int i = 0; i < 8; i++) {
            float e = __expf(pm[i * 32 + t] - M);
            L += pl[i * 32 + t] * e;
#pragma unroll
            for (int d = 0; d < DH; d++) vacc[d] += pac[(i * 32 + t) * 33 + d] * e;
        }
        float inv = 1.f / L;
        int qo = blockIdx.x * 32 + t;
#pragma unroll
        for (int d = 0; d < DH; d++)
            g_ctx[(b * S + qo) * E + h * DH + d] = vacc[d] * inv;
    }
}

// ---------------- kernel 4: gpb = ctx @ W_comb^T + b_comb ----------------
__global__ void gproj_kernel() {
    extern __shared__ float sh[];
    float* cs = sh;          // 32*260
    float* ws = sh + 8320;   // 16*268
    const int t = threadIdx.x;
    const int chunk = blockIdx.x, stile = blockIdx.y, b = blockIdx.z;
    const int s0 = stile * 32;
    for (int p = 0; p < 8; p++) {
        int i4 = t + p * 256;
        int s = i4 >> 6, e4 = i4 & 63;
        *(float4*)&cs[s * 260 + 4 * e4] = *(const float4*)&g_ctx[(b * S + s0 + s) * E + 4 * e4];
    }
    for (int p = 0; p < 4; p++) {
        int i4 = t + p * 256;
        int o = i4 >> 6, k4 = i4 & 63;
        int c = chunk * 16 + o;
        float4 v0 = *(const float4*)&g_wpart[(c) * 256 + 4 * k4];
        float4 v1 = *(const float4*)&g_wpart[(128 + c) * 256 + 4 * k4];
        float4 v2 = *(const float4*)&g_wpart[(256 + c) * 256 + 4 * k4];
        float4 v3 = *(const float4*)&g_wpart[(384 + c) * 256 + 4 * k4];
        v0.x += v1.x + v2.x + v3.x;
        v0.y += v1.y + v2.y + v3.y;
        v0.z += v1.z + v2.z + v3.z;
        v0.w += v1.w + v2.w + v3.w;
        *(float4*)&ws[o * 268 + 4 * k4] = v0;
    }
    __syncthreads();
    const int ol = t & 15, sg = t >> 4;
    float acc[2] = {0.f, 0.f};
#pragma unroll 8
    for (int k4 = 0; k4 < 64; k4++) {
        float4 wv = *(float4*)&ws[ol * 268 + 4 * k4];
#pragma unroll
        for (int i = 0; i < 2; i++) {
            float4 av = *(float4*)&cs[(sg + 16 * i) * 260 + 4 * k4];
            acc[i] += wv.x * av.x + wv.y * av.y + wv.z * av.z + wv.w * av.w;
        }
    }
    const int og = chunk * 16 + ol;
    const float bb = g_bcomb[og];
#pragma unroll
    for (int i = 0; i < 2; i++)
        g_gpb[(b * S + s0 + sg + 16 * i) * 128 + og] = acc[i] + bb;
}

// ---------------- kernel 5: fp16 mma.sync point-MLP (hi-only W, gpb init) ----------------
#define AB(i)   ((i) ? 18432 : 0)
#define MT_H3   0
#define MT_BI3  36864
#define MT_W4S  37120
#define MT_PREF 37632
#define MT_CID  38660
#define MT_SIZE 39424

__global__ __launch_bounds__(256)
void mlp_mma_kernel(const float* __restrict__ lo, const float* __restrict__ w4,
                    const float* __restrict__ b4, float* __restrict__ out) {
    extern __shared__ __align__(16) char smc[];
    float* h3f  = (float*)(smc + MT_H3);
    float* bi3s = (float*)(smc + MT_BI3);
    float* w4s  = (float*)(smc + MT_W4S);
    int*   pref = (int*)(smc + MT_PREF);
    int*   cid  = (int*)(smc + MT_CID);
    const unsigned smemB = (unsigned)__cvta_generic_to_shared(smc);

    const int t = threadIdx.x;
    const int w = t >> 5, lane = t & 31;
    const int b = blockIdx.y;
    const int n0 = blockIdx.x * 128;

    if (t < 128) w4s[t] = w4[t];
    if (t >= 128 && t < 192) bi3s[t - 128] = g_bi3[t - 128];
    if (t < 256) pref[t] = g_pref[t];
    __syncthreads();
    if (t < 128) {
        int i = n0 + t;
        int s = 0;
#pragma unroll
        for (int step = 128; step >= 1; step >>= 1)
            if (s + step <= 255 && pref[s + step] <= i) s += step;
        cid[t] = s;
    }
    __syncthreads();

    const int grow = t >> 1, gkh = (t & 1) * 32;
    const int arow = (lane & 7) + ((lane >> 3) & 1) * 8;
    const int akb  = (lane >> 4) * 16;
    const int wm = w >> 2, wn = w & 3;
    const int g = lane >> 2, tg = lane & 3;

    // ---- gather chunk 0 (lo k 0-63) ----
    {
        const float* src = lo + ((size_t)(b * NN + n0 + grow)) * LD + gkh;
        unsigned hb = smemB + AB(0) + grow * 144 + gkh * 2;
#pragma unroll
        for (int j = 0; j < 8; j++) {
            float4 v = *(const float4*)(src + 4 * j);
            sts64(hb + 8 * j, pack2h(v.x, v.y), pack2h(v.z, v.w));
        }
    }

    // ---- init accumulators from gpb[cid] ----
    float acc[4][4][4];
#pragma unroll
    for (int mt = 0; mt < 4; mt++) {
        int r0 = wm * 64 + mt * 16 + g;
        const float* g0 = g_gpb + ((size_t)(b * S + cid[r0])) * 128;
        const float* g1 = g_gpb + ((size_t)(b * S + cid[r0 + 8])) * 128;
#pragma unroll
        for (int nt = 0; nt < 4; nt++) {
            int col = wn * 32 + nt * 8 + 2 * tg;
            float2 v0 = *(const float2*)(g0 + col);
            float2 v1 = *(const float2*)(g1 + col);
            acc[mt][nt][0] = v0.x; acc[mt][nt][1] = v0.y;
            acc[mt][nt][2] = v1.x; acc[mt][nt][3] = v1.y;
        }
    }
    __syncthreads();

    // ---- stage 1: 2 chunks of K=64 (lo only), hi-only ----
    for (int c = 0; c < 2; c++) {
        float4 nxt[8];
        if (c == 0) {
            const float* src = lo + ((size_t)(b * NN + n0 + grow)) * LD + 64 + gkh;
#pragma unroll
            for (int j = 0; j < 8; j++) nxt[j] = *(const float4*)(src + 4 * j);
        }
        const unsigned ah = smemB + AB(c);
#pragma unroll
        for (int ks = 0; ks < 4; ks++) {
            uint2 bh[4];
#pragma unroll
            for (int nt = 0; nt < 4; nt++) {
                int idx = ((c * 4 + ks) * 16 + wn * 4 + nt) * 32 + lane;
                bh[nt] = __ldg(&g_w2fh[idx]);
            }
#pragma unroll
            for (int mt = 0; mt < 4; mt++) {
                unsigned base = (wm * 64 + mt * 16 + arow) * 144 + ks * 32 + akb;
                unsigned fah[4];
                ldmx4(fah, ah + base);
#pragma unroll
                for (int nt = 0; nt < 4; nt++)
                    mma_f16(acc[mt][nt][0], acc[mt][nt][1], acc[mt][nt][2], acc[mt][nt][3],
                            fah, bh[nt].x, bh[nt].y);
            }
        }
        if (c == 0) {
            unsigned hb = smemB + AB(1) + grow * 144 + gkh * 2;
#pragma unroll
            for (int j = 0; j < 8; j++)
                sts64(hb + 8 * j, pack2h(nxt[j].x, nxt[j].y), pack2h(nxt[j].z, nxt[j].w));
        }
        __syncthreads();
    }

    // ---- stage1 epilogue: relu -> fp16 h2 into A buffers ----
    {
#pragma unroll
        for (int mt = 0; mt < 4; mt++) {
#pragma unroll
            for (int nt = 0; nt < 4; nt++) {
                int col = wn * 32 + nt * 8 + 2 * tg;
                int bufi = col >> 6;
                unsigned off = (col & 63) * 2;
                int r0 = wm * 64 + mt * 16 + g;
                *(unsigned*)(smc + AB(bufi) + r0 * 144 + off) =
                    pack2h(fmaxf(acc[mt][nt][0], 0.f), fmaxf(acc[mt][nt][1], 0.f));
                int r1 = r0 + 8;
                *(unsigned*)(smc + AB(bufi) + r1 * 144 + off) =
                    pack2h(fmaxf(acc[mt][nt][2], 0.f), fmaxf(acc[mt][nt][3], 0.f));
            }
        }
    }
    __syncthreads();

    // ---- stage 2: K=128 (8 ksteps), warp tile 32 pts x 32 ch, hi-only ----
    const int wm2 = w >> 1, wn2 = w & 1;
    float ac2[2][4][4];
#pragma unroll
    for (int mt = 0; mt < 2; mt++)
#pragma unroll
        for (int nt = 0; nt < 4; nt++)
#pragma unroll
            for (int r = 0; r < 4; r++) ac2[mt][nt][r] = 0.f;

#pragma unroll
    for (int ks = 0; ks < 8; ks++) {
        const unsigned ah = smemB + AB(ks >> 2);
        const int ki = ks & 3;
        uint2 bh[4];
#pragma unroll
        for (int nt = 0; nt < 4; nt++) {
            int idx = (ks * 8 + wn2 * 4 + nt) * 32 + lane;
            bh[nt] = __ldg(&g_w3fh[idx]);
        }
#pragma unroll
        for (int mt = 0; mt < 2; mt++) {
            unsigned base = (wm2 * 32 + mt * 16 + arow) * 144 + ki * 32 + akb;
            unsigned fah[4];
            ldmx4(fah, ah + base);
#pragma unroll
            for (int nt = 0; nt < 4; nt++)
                mma_f16(ac2[mt][nt][0], ac2[mt][nt][1], ac2[mt][nt][2], ac2[mt][nt][3],
                        fah, bh[nt].x, bh[nt].y);
        }
    }
    __syncthreads();

    // ---- stage2 epilogue: h3 fp32 overlay ----
    {
#pragma unroll
        for (int mt = 0; mt < 2; mt++) {
#pragma unroll
            for (int nt = 0; nt < 4; nt++) {
                int col = wn2 * 32 + nt * 8 + 2 * tg;
                float bia = bi3s[col], bib = bi3s[col + 1];
                int r0 = wm2 * 32 + mt * 16 + g;
                h3f[r0 * 67 + col]     = fmaxf(ac2[mt][nt][0] + bia, 0.f);
                h3f[r0 * 67 + col + 1] = fmaxf(ac2[mt][nt][1] + bib, 0.f);
                int r1 = r0 + 8;
                h3f[r1 * 67 + col]     = fmaxf(ac2[mt][nt][2] + bia, 0.f);
                h3f[r1 * 67 + col + 1] = fmaxf(ac2[mt][nt][3] + bib, 0.f);
            }
        }
    }
    __syncthreads();

    // ---- conv4 + transposed write ----
    if (t < 128) {
        const int p = t;
        float a0 = b4[0], a1 = b4[1];
#pragma unroll
        for (int k = 0; k < 64; k++) {
            float v = h3f[p * 67 + k];
            a0 += v * w4s[k];
            a1 += v * w4s[64 + k];
        }
        out[(size_t)(b * NC + 0) * NN + n0 + p] = a0;
        out[(size_t)(b * NC + 1) * NN + n0 + p] = a1;
    }
}

// ---------------- launch ----------------
extern "C" void kernel_launch(void* const* d_in, const int* in_sizes, int n_in,
                              void* d_out, int out_size) {
    const float* gl   = (const float*)d_in[0];
    const float* lo   = (const float*)d_in[1];
    const float* cent = (const float*)d_in[2];
    const int*   npc  = (const int*)  d_in[3];
    const float* fc1w = (const float*)d_in[4];
    const float* fc1b = (const float*)d_in[5];
    const float* fc2w = (const float*)d_in[6];
    const float* fc2b = (const float*)d_in[7];
    const float* inw  = (const float*)d_in[8];
    const float* inb  = (const float*)d_in[9];
    const float* ow   = (const float*)d_in[10];
    const float* ob   = (const float*)d_in[11];
    const float* w2   = (const float*)d_in[12];
    const float* cb2  = (const float*)d_in[13];
    const float* gm2  = (const float*)d_in[14];
    const float* bt2  = (const float*)d_in[15];
    const float* mu2  = (const float*)d_in[16];
    const float* va2  = (const float*)d_in[17];
    const float* w3   = (const float*)d_in[18];
    const float* cb3  = (const float*)d_in[19];
    const float* gm3  = (const float*)d_in[20];
    const float* bt3  = (const float*)d_in[21];
    const float* mu3  = (const float*)d_in[22];
    const float* va3  = (const float*)d_in[23];
    const float* w4   = (const float*)d_in[24];
    const float* b4   = (const float*)d_in[25];
    float* out = (float*)d_out;

    const int attn_smem = (8192 * 2 + 256 * 2 + 8448) * 4;
    const int gp_smem   = (8320 + 16 * 268) * 4;

    cudaFuncSetAttribute(xqkv_kernel,    cudaFuncAttributeMaxDynamicSharedMemorySize, XQ_SMEM);
    cudaFuncSetAttribute(attn_kernel,    cudaFuncAttributeMaxDynamicSharedMemorySize, attn_smem);
    cudaFuncSetAttribute(gproj_kernel,   cudaFuncAttributeMaxDynamicSharedMemorySize, gp_smem);
    cudaFuncSetAttribute(mlp_mma_kernel, cudaFuncAttributeMaxDynamicSharedMemorySize, MT_SIZE);

    setup1_kernel<<<849, 256>>>(npc, cent, fc1w, fc1b, fc2w, fc2b, inw, ow, ob,
                                w2, cb2, gm2, bt2, mu2, va2,
                                w3, cb3, gm3, bt3, mu3, va3);
    xqkv_kernel<<<dim3(12, 4, B), 256, XQ_SMEM>>>(gl, inb);
    attn_kernel<<<dim3(8, H, B), 256, attn_smem>>>();
    gproj_kernel<<<dim3(8, 8, B), 256, gp_smem>>>();
    mlp_mma_kernel<<<dim3(NN / 128, B), 256, MT_SIZE>>>(lo, w4, b4, out);
}